// round 10
// baseline (speedup 1.0000x reference)
#include <cuda_runtime.h>
#include <cuda.h>
#include <cstdint>

#define DIM 256
#define OUT 8
#define CHUNK 32           // floats per chunk = 128B row piece (SW128 box width)
#define NCHUNK 8           // DIM / CHUNK
#define TPB 256            // tokens per block group (1 per thread)
#define STAGES 3

#define TILE_BYTES  (TPB * CHUNK * 4)          // 32768 per stage
#define XBUF_BYTES  (STAGES * TILE_BYTES)      // 98304
#define WP_BYTES    (DIM / 2 * OUT * 8)        // 8192
#define MBAR_BYTES  (2 * STAGES * 8)           // full[3] + empty[3]
#define SMEM_TOTAL  (1024 + XBUF_BYTES + WP_BYTES + 64 + 96 * 4)

__device__ __forceinline__ unsigned long long pk2(float lo, float hi) {
    unsigned long long r;
    asm("mov.b64 %0, {%1,%2};" : "=l"(r) : "f"(lo), "f"(hi));
    return r;
}
__device__ __forceinline__ unsigned long long fma2(unsigned long long a, unsigned long long b,
                                                   unsigned long long c) {
    unsigned long long d;
    asm("fma.rn.f32x2 %0, %1, %2, %3;" : "=l"(d) : "l"(a), "l"(b), "l"(c));
    return d;
}
__device__ __forceinline__ void mbar_init(uint32_t mbar, uint32_t cnt) {
    asm volatile("mbarrier.init.shared.b64 [%0], %1;" :: "r"(mbar), "r"(cnt) : "memory");
}
__device__ __forceinline__ void mbar_expect_tx(uint32_t mbar, uint32_t bytes) {
    asm volatile("mbarrier.arrive.expect_tx.shared.b64 _, [%0], %1;" :: "r"(mbar), "r"(bytes) : "memory");
}
__device__ __forceinline__ void mbar_arrive(uint32_t mbar) {
    asm volatile("mbarrier.arrive.shared.b64 _, [%0];" :: "r"(mbar) : "memory");
}
__device__ __forceinline__ void mbar_wait(uint32_t mbar, uint32_t parity) {
    uint32_t done;
    asm volatile(
        "{\n\t.reg .pred p;\n\t"
        "mbarrier.try_wait.parity.acquire.cta.shared::cta.b64 p, [%1], %2;\n\t"
        "selp.b32 %0, 1, 0, p;\n\t}"
        : "=r"(done) : "r"(mbar), "r"(parity) : "memory");
    if (!done) {
        asm volatile(
            "{\n\t.reg .pred P1;\n\t"
            "WL_%=:\n\t"
            "mbarrier.try_wait.parity.acquire.cta.shared::cta.b64 P1, [%0], %1, 0x989680;\n\t"
            "@P1 bra.uni WD_%=;\n\t"
            "bra.uni WL_%=;\n\t"
            "WD_%=:\n\t}"
            :: "r"(mbar), "r"(parity) : "memory");
    }
}
__device__ __forceinline__ void tma_load_2d(uint32_t dst, const void* tmap,
                                            int cx, int cy, uint32_t mbar) {
    asm volatile(
        "cp.async.bulk.tensor.2d.shared::cta.global.tile.mbarrier::complete_tx::bytes "
        "[%0], [%1, {%2, %3}], [%4];"
        :: "r"(dst), "l"(tmap), "r"(cx), "r"(cy), "r"(mbar) : "memory");
}

struct EpiParams { const float *W2, *b1, *b2, *g, *bt; };

__device__ __forceinline__ void epilogue(const unsigned long long* acc, const EpiParams& ep,
                                         float* __restrict__ out, int tok)
{
    float gg[OUT];
    #pragma unroll
    for (int o = 0; o < OUT; o++) {
        float2 p = *(const float2*)&acc[o];
        float hv = p.x + p.y + ep.b1[o];
        gg[o] = 0.5f * hv * (1.0f + erff(hv * 0.70710678118654752440f));
    }
    float y[OUT];
    #pragma unroll
    for (int p = 0; p < OUT; p++) {
        float s = ep.b2[p];
        #pragma unroll
        for (int o = 0; o < OUT; o++) s = fmaf(ep.W2[p * 8 + o], gg[o], s);
        y[p] = s;
    }
    float mu = 0.0f;
    #pragma unroll
    for (int p = 0; p < OUT; p++) mu += y[p];
    mu *= 0.125f;
    float var = 0.0f;
    #pragma unroll
    for (int p = 0; p < OUT; p++) { float d = y[p] - mu; var = fmaf(d, d, var); }
    var *= 0.125f;
    float rs = rsqrtf(var + 1e-5f);

    float4 o0, o1;
    o0.x = (y[0] - mu) * rs * ep.g[0] + ep.bt[0];
    o0.y = (y[1] - mu) * rs * ep.g[1] + ep.bt[1];
    o0.z = (y[2] - mu) * rs * ep.g[2] + ep.bt[2];
    o0.w = (y[3] - mu) * rs * ep.g[3] + ep.bt[3];
    o1.x = (y[4] - mu) * rs * ep.g[4] + ep.bt[4];
    o1.y = (y[5] - mu) * rs * ep.g[5] + ep.bt[5];
    o1.z = (y[6] - mu) * rs * ep.g[6] + ep.bt[6];
    o1.w = (y[7] - mu) * rs * ep.g[7] + ep.bt[7];
    float4* op = (float4*)(out + (size_t)tok * 8);
    op[0] = o0;
    op[1] = o1;
}

__global__ __launch_bounds__(256, 2)
void ffn_kernel(const __grid_constant__ CUtensorMap tmap,
                const float* __restrict__ W1, const float* __restrict__ b1,
                const float* __restrict__ W2, const float* __restrict__ b2,
                const float* __restrict__ gamma, const float* __restrict__ beta,
                float* __restrict__ out, int ntok)
{
    extern __shared__ char smem_raw[];
    char* smem = (char*)(((uintptr_t)smem_raw + 1023) & ~(uintptr_t)1023);   // 1KB-align for SW128
    float* xtile = (float*)smem;                                  // 3 x 32KB stages
    unsigned long long* Wp = (unsigned long long*)(smem + XBUF_BYTES);
    unsigned long long* mbar = (unsigned long long*)(smem + XBUF_BYTES + WP_BYTES);
    float* tail = (float*)(smem + XBUF_BYTES + WP_BYTES + 64);
    float* sW2 = tail;          // 64
    float* sb1 = tail + 64;     // 8
    float* sb2 = tail + 72;     // 8
    float* sg  = tail + 80;     // 8
    float* sbt = tail + 88;     // 8

    const int tid = threadIdx.x;
    const uint32_t mbar_su  = (uint32_t)__cvta_generic_to_shared(mbar);
    const uint32_t xtile_su = (uint32_t)__cvta_generic_to_shared(xtile);

    // ---- one-time init ----
    {
        int e = tid * 4;
        #pragma unroll
        for (int q = 0; q < 4; q++) {
            int idx = e + q;
            int d = idx >> 3;
            int o = idx & 7;
            Wp[idx] = pk2(W1[o * DIM + 2 * d], W1[o * DIM + 2 * d + 1]);
        }
        if (tid < 64) sW2[tid] = W2[tid];
        if (tid < 8) { sb1[tid] = b1[tid]; sb2[tid] = b2[tid]; sg[tid] = gamma[tid]; sbt[tid] = beta[tid]; }
        if (tid == 0) {
            #pragma unroll
            for (int s = 0; s < STAGES; s++) {
                mbar_init(mbar_su + s * 8, 1);                  // full[s]: TMA complete_tx
                mbar_init(mbar_su + (STAGES + s) * 8, TPB);     // empty[s]: all threads arrive
            }
        }
    }
    __syncthreads();

    const int ngroups = (ntok + TPB - 1) / TPB;
    EpiParams ep{sW2, sb1, sb2, sg, sbt};
    const ulonglong2* Wp2 = (const ulonglong2*)Wp;
    const int t7 = tid & 7;
    const float* myrow = xtile + tid * CHUNK;                    // this thread's row in stage 0

    // per-stage mbarrier phase state
    uint32_t fc0 = 0, fc1 = 0, fc2 = 0;        // consumer full-parity
    uint32_t pe0 = 1, pe1 = 1, pe2 = 1;        // producer empty-parity (flipped: first wait passes)

    for (int g = blockIdx.x; g < ngroups; g += gridDim.x) {
        const int base = g * TPB;

        // ---- producer: issue chunk c into stage s (tid 0) ----
        auto produce = [&](int c) {
            const int s = c % STAGES;
            uint32_t eb = mbar_su + (STAGES + s) * 8;
            uint32_t fb = mbar_su + s * 8;
            uint32_t pe = (s == 0) ? pe0 : (s == 1) ? pe1 : pe2;
            mbar_wait(eb, pe);
            if (s == 0) pe0 ^= 1; else if (s == 1) pe1 ^= 1; else pe2 ^= 1;
            mbar_expect_tx(fb, TILE_BYTES);
            tma_load_2d(xtile_su + s * TILE_BYTES, &tmap, c * CHUNK, base, fb);
        };

        unsigned long long acc[OUT];
        #pragma unroll
        for (int o = 0; o < OUT; o++) acc[o] = 0ull;

        if (tid == 0) { produce(0); produce(1); produce(2); }

        #pragma unroll
        for (int c = 0; c < NCHUNK; c++) {
            const int s = c % STAGES;
            // wait full[s]
            {
                uint32_t fb = mbar_su + s * 8;
                uint32_t fcv = (s == 0) ? fc0 : (s == 1) ? fc1 : fc2;
                mbar_wait(fb, fcv);
                if (s == 0) fc0 ^= 1; else if (s == 1) fc1 ^= 1; else fc2 ^= 1;
            }
            // compute chunk c from stage s (SW128: piece i at phys i^(tid&7) within row)
            {
                const float* r = myrow + s * (TILE_BYTES / 4);
                #pragma unroll
                for (int i = 0; i < 8; i++) {
                    ulonglong2 xv = *(const ulonglong2*)(r + ((i ^ t7) << 2));
                    const int dpg = c * 16 + 2 * i;
                    const ulonglong2* w = Wp2 + (size_t)dpg * 4;
                    {
                        ulonglong2 w0 = w[0];
                        acc[0] = fma2(xv.x, w0.x, acc[0]);
                        acc[1] = fma2(xv.x, w0.y, acc[1]);
                        ulonglong2 w1 = w[1];
                        acc[2] = fma2(xv.x, w1.x, acc[2]);
                        acc[3] = fma2(xv.x, w1.y, acc[3]);
                        ulonglong2 w2 = w[2];
                        acc[4] = fma2(xv.x, w2.x, acc[4]);
                        acc[5] = fma2(xv.x, w2.y, acc[5]);
                        ulonglong2 w3 = w[3];
                        acc[6] = fma2(xv.x, w3.x, acc[6]);
                        acc[7] = fma2(xv.x, w3.y, acc[7]);
                    }
                    {
                        ulonglong2 w4 = w[4];
                        acc[0] = fma2(xv.y, w4.x, acc[0]);
                        acc[1] = fma2(xv.y, w4.y, acc[1]);
                        ulonglong2 w5 = w[5];
                        acc[2] = fma2(xv.y, w5.x, acc[2]);
                        acc[3] = fma2(xv.y, w5.y, acc[3]);
                        ulonglong2 w6 = w[6];
                        acc[4] = fma2(xv.y, w6.x, acc[4]);
                        acc[5] = fma2(xv.y, w6.y, acc[5]);
                        ulonglong2 w7 = w[7];
                        acc[6] = fma2(xv.y, w7.x, acc[6]);
                        acc[7] = fma2(xv.y, w7.y, acc[7]);
                    }
                }
            }
            // release stage, then producer refills
            mbar_arrive(mbar_su + (STAGES + s) * 8);
            if (tid == 0 && c + STAGES < NCHUNK) produce(c + STAGES);
        }

        // ---- epilogue: this thread owns token base+tid (OOB rows zero-filled by TMA) ----
        const int tok = base + tid;
        if (tok < ntok) epilogue(acc, ep, out, tok);
    }
}

extern "C" void kernel_launch(void* const* d_in, const int* in_sizes, int n_in,
                              void* d_out, int out_size)
{
    const float* x     = (const float*)d_in[0];
    const float* W1    = (const float*)d_in[1];
    const float* b1    = (const float*)d_in[2];
    const float* W2    = (const float*)d_in[3];
    const float* b2    = (const float*)d_in[4];
    const float* gamma = (const float*)d_in[5];
    const float* beta  = (const float*)d_in[6];
    float* out = (float*)d_out;

    int ntok = in_sizes[0] / DIM;               // 262144 for the bench shape

    // ---- build TMA descriptor (driver entry point via runtime; no -lcuda link) ----
    typedef CUresult (*PFN_enc)(CUtensorMap*, CUtensorMapDataType, cuuint32_t, void*,
                                const cuuint64_t*, const cuuint64_t*, const cuuint32_t*,
                                const cuuint32_t*, CUtensorMapInterleave, CUtensorMapSwizzle,
                                CUtensorMapL2promotion, CUtensorMapFloatOOBfill);
    void* sym = nullptr;
    cudaDriverEntryPointQueryResult qst;
    cudaGetDriverEntryPoint("cuTensorMapEncodeTiled", &sym, cudaEnableDefault, &qst);
    PFN_enc enc = (PFN_enc)sym;

    CUtensorMap tmap;
    cuuint64_t dims[2]    = {(cuuint64_t)DIM, (cuuint64_t)ntok};
    cuuint64_t strides[1] = {(cuuint64_t)DIM * 4};                  // 1024B row stride
    cuuint32_t box[2]     = {(cuuint32_t)CHUNK, (cuuint32_t)TPB};   // 128B x 256 rows = 32KB
    cuuint32_t es[2]      = {1, 1};
    enc(&tmap, CU_TENSOR_MAP_DATA_TYPE_FLOAT32, 2, (void*)x,
        dims, strides, box, es,
        CU_TENSOR_MAP_INTERLEAVE_NONE, CU_TENSOR_MAP_SWIZZLE_128B,
        CU_TENSOR_MAP_L2_PROMOTION_L2_128B, CU_TENSOR_MAP_FLOAT_OOB_FILL_NONE);

    int ngroups = (ntok + TPB - 1) / TPB;
    int blocks = 296;                            // 2 blocks/SM resident, grid-stride
    if (blocks > ngroups) blocks = ngroups;
    if (blocks < 1) blocks = 1;

    cudaFuncSetAttribute(ffn_kernel, cudaFuncAttributeMaxDynamicSharedMemorySize, SMEM_TOTAL);
    ffn_kernel<<<blocks, 256, SMEM_TOTAL>>>(tmap, W1, b1, W2, b2, gamma, beta, out, ntok);
}

// round 11
// speedup vs baseline: 1.6563x; 1.6563x over previous
#include <cuda_runtime.h>
#include <cuda.h>
#include <cstdint>

#define DIM 256
#define OUT 8
#define TPW 32             // tokens per warp group
#define WARPS 8            // warps per block, 1 block/SM
#define STAGE_BYTES 8192   // 2 chunks x 32 tokens x 128B
#define STAGE_FLOATS (STAGE_BYTES / 4)

#define XBUF_BYTES  (WARPS * 2 * STAGE_BYTES)   // 131072
#define WP_BYTES    (DIM / 2 * OUT * 8)         // 8192
#define SMEM_TOTAL  (1024 + XBUF_BYTES + WP_BYTES + 16 * 8 + 96 * 4)

__device__ __forceinline__ unsigned long long pk2(float lo, float hi) {
    unsigned long long r;
    asm("mov.b64 %0, {%1,%2};" : "=l"(r) : "f"(lo), "f"(hi));
    return r;
}
__device__ __forceinline__ unsigned long long fma2(unsigned long long a, unsigned long long b,
                                                   unsigned long long c) {
    unsigned long long d;
    asm("fma.rn.f32x2 %0, %1, %2, %3;" : "=l"(d) : "l"(a), "l"(b), "l"(c));
    return d;
}
__device__ __forceinline__ void mbar_init(uint32_t mbar, uint32_t cnt) {
    asm volatile("mbarrier.init.shared.b64 [%0], %1;" :: "r"(mbar), "r"(cnt) : "memory");
}
__device__ __forceinline__ void mbar_expect_tx(uint32_t mbar, uint32_t bytes) {
    asm volatile("mbarrier.arrive.expect_tx.shared.b64 _, [%0], %1;" :: "r"(mbar), "r"(bytes) : "memory");
}
__device__ __forceinline__ void mbar_wait(uint32_t mbar, uint32_t parity) {
    uint32_t done;
    asm volatile(
        "{\n\t.reg .pred p;\n\t"
        "mbarrier.try_wait.parity.acquire.cta.shared::cta.b64 p, [%1], %2;\n\t"
        "selp.b32 %0, 1, 0, p;\n\t}"
        : "=r"(done) : "r"(mbar), "r"(parity) : "memory");
    if (!done) {
        asm volatile(
            "{\n\t.reg .pred P1;\n\t"
            "WL_%=:\n\t"
            "mbarrier.try_wait.parity.acquire.cta.shared::cta.b64 P1, [%0], %1, 0x989680;\n\t"
            "@P1 bra.uni WD_%=;\n\t"
            "bra.uni WL_%=;\n\t"
            "WD_%=:\n\t}"
            :: "r"(mbar), "r"(parity) : "memory");
    }
}
__device__ __forceinline__ void tma_load_3d(uint32_t dst, const void* tmap,
                                            int c0, int c1, int c2, uint32_t mbar) {
    asm volatile(
        "cp.async.bulk.tensor.3d.shared::cta.global.tile.mbarrier::complete_tx::bytes "
        "[%0], [%1, {%2, %3, %4}], [%5];"
        :: "r"(dst), "l"(tmap), "r"(c0), "r"(c1), "r"(c2), "r"(mbar) : "memory");
}

struct EpiParams { const float *W2, *b1, *b2, *g, *bt; };

__device__ __forceinline__ void epilogue(const unsigned long long* acc, const EpiParams& ep,
                                         float* __restrict__ out, int tok)
{
    float gg[OUT];
    #pragma unroll
    for (int o = 0; o < OUT; o++) {
        float2 p = *(const float2*)&acc[o];
        float hv = p.x + p.y + ep.b1[o];
        gg[o] = 0.5f * hv * (1.0f + erff(hv * 0.70710678118654752440f));
    }
    float y[OUT];
    #pragma unroll
    for (int p = 0; p < OUT; p++) {
        float s = ep.b2[p];
        #pragma unroll
        for (int o = 0; o < OUT; o++) s = fmaf(ep.W2[p * 8 + o], gg[o], s);
        y[p] = s;
    }
    float mu = 0.0f;
    #pragma unroll
    for (int p = 0; p < OUT; p++) mu += y[p];
    mu *= 0.125f;
    float var = 0.0f;
    #pragma unroll
    for (int p = 0; p < OUT; p++) { float d = y[p] - mu; var = fmaf(d, d, var); }
    var *= 0.125f;
    float rs = rsqrtf(var + 1e-5f);

    float4 o0, o1;
    o0.x = (y[0] - mu) * rs * ep.g[0] + ep.bt[0];
    o0.y = (y[1] - mu) * rs * ep.g[1] + ep.bt[1];
    o0.z = (y[2] - mu) * rs * ep.g[2] + ep.bt[2];
    o0.w = (y[3] - mu) * rs * ep.g[3] + ep.bt[3];
    o1.x = (y[4] - mu) * rs * ep.g[4] + ep.bt[4];
    o1.y = (y[5] - mu) * rs * ep.g[5] + ep.bt[5];
    o1.z = (y[6] - mu) * rs * ep.g[6] + ep.bt[6];
    o1.w = (y[7] - mu) * rs * ep.g[7] + ep.bt[7];
    float4* op = (float4*)(out + (size_t)tok * 8);
    op[0] = o0;
    op[1] = o1;
}

__global__ __launch_bounds__(256, 1)
void ffn_kernel(const __grid_constant__ CUtensorMap tmap,
                const float* __restrict__ W1, const float* __restrict__ b1,
                const float* __restrict__ W2, const float* __restrict__ b2,
                const float* __restrict__ gamma, const float* __restrict__ beta,
                float* __restrict__ out, int ntok)
{
    extern __shared__ char smem_raw[];
    char* smem = (char*)(((uintptr_t)smem_raw + 1023) & ~(uintptr_t)1023);
    float* xbuf = (float*)smem;                                   // 8 warps x 2 x 8KB
    unsigned long long* Wp = (unsigned long long*)(smem + XBUF_BYTES);
    unsigned long long* mbar = (unsigned long long*)(smem + XBUF_BYTES + WP_BYTES);
    float* tail = (float*)(smem + XBUF_BYTES + WP_BYTES + 16 * 8);
    float* sW2 = tail;          // 64
    float* sb1 = tail + 64;     // 8
    float* sb2 = tail + 72;     // 8
    float* sg  = tail + 80;     // 8
    float* sbt = tail + 88;     // 8

    const int tid = threadIdx.x;
    const uint32_t mbar_su = (uint32_t)__cvta_generic_to_shared(mbar);

    // ---- one-time init: packed W1 dim-pairs + params + per-warp mbarriers ----
    {
        int e = tid * 4;
        #pragma unroll
        for (int q = 0; q < 4; q++) {
            int idx = e + q;
            int d = idx >> 3;
            int o = idx & 7;
            Wp[idx] = pk2(W1[o * DIM + 2 * d], W1[o * DIM + 2 * d + 1]);
        }
        if (tid < 64) sW2[tid] = W2[tid];
        if (tid < 8) { sb1[tid] = b1[tid]; sb2[tid] = b2[tid]; sg[tid] = gamma[tid]; sbt[tid] = beta[tid]; }
        if (tid < 16) mbar_init(mbar_su + tid * 8, 1);
    }
    __syncthreads();

    const int lane = tid & 31;
    const int warp = tid >> 5;
    const int warp_global = blockIdx.x * WARPS + warp;
    const int nwarps = gridDim.x * WARPS;
    const int ngroups = (ntok + TPW - 1) / TPW;

    float* wtile = xbuf + warp * 2 * STAGE_FLOATS;
    const uint32_t wtile_su = (uint32_t)__cvta_generic_to_shared(wtile);
    const uint32_t mb0 = mbar_su + warp * 16;       // full[s0]
    const uint32_t mb1 = mb0 + 8;                   // full[s1]
    EpiParams ep{sW2, sb1, sb2, sg, sbt};
    const ulonglong2* Wp2 = (const ulonglong2*)Wp;

    uint32_t ph0 = 0, ph1 = 0;

    // issue stage-pair cp (cpair = 0 or 1 -> chunks [2*cpair, 2*cpair+1]) for token base
    auto produce = [&](int base, int cpair) {
        if (lane == 0) {
            const int s = cpair & 1;
            uint32_t mb = s ? mb1 : mb0;
            mbar_expect_tx(mb, STAGE_BYTES);
            tma_load_3d(wtile_su + s * STAGE_BYTES, &tmap, 0, cpair * 2, base, mb);
        }
    };

    if (warp_global < ngroups) {
        const int base0 = warp_global * TPW;
        produce(base0, 0);
        produce(base0, 1);
    }

    for (int g = warp_global; g < ngroups; g += nwarps) {
        const int base = g * TPW;
        const int gn = g + nwarps;
        const int basen = gn * TPW;

        unsigned long long acc[OUT];
        #pragma unroll
        for (int o = 0; o < OUT; o++) acc[o] = 0ull;

        #pragma unroll
        for (int c2 = 0; c2 < 4; c2++) {
            const int s = c2 & 1;
            if (s == 0) { mbar_wait(mb0, ph0); ph0 ^= 1; }
            else        { mbar_wait(mb1, ph1); ph1 ^= 1; }

            // compute chunks 2*c2, 2*c2+1 from stage s
            // smem layout per stage: [token][clocal(2)][128B], SW128-swizzled
            const float* sb = wtile + s * STAGE_FLOATS;
            #pragma unroll
            for (int cl = 0; cl < 2; cl++) {
                const int r = lane * 2 + cl;
                const float* row = sb + r * 32;
                const int r7 = r & 7;
                const int c = c2 * 2 + cl;
                #pragma unroll
                for (int i = 0; i < 8; i++) {
                    ulonglong2 xv = *(const ulonglong2*)(row + ((i ^ r7) << 2));
                    const int dpg = c * 16 + 2 * i;
                    const ulonglong2* w = Wp2 + (size_t)dpg * 4;
                    {
                        ulonglong2 w0 = w[0];
                        acc[0] = fma2(xv.x, w0.x, acc[0]);
                        acc[1] = fma2(xv.x, w0.y, acc[1]);
                        ulonglong2 w1 = w[1];
                        acc[2] = fma2(xv.x, w1.x, acc[2]);
                        acc[3] = fma2(xv.x, w1.y, acc[3]);
                        ulonglong2 w2 = w[2];
                        acc[4] = fma2(xv.x, w2.x, acc[4]);
                        acc[5] = fma2(xv.x, w2.y, acc[5]);
                        ulonglong2 w3 = w[3];
                        acc[6] = fma2(xv.x, w3.x, acc[6]);
                        acc[7] = fma2(xv.x, w3.y, acc[7]);
                    }
                    {
                        ulonglong2 w4 = w[4];
                        acc[0] = fma2(xv.y, w4.x, acc[0]);
                        acc[1] = fma2(xv.y, w4.y, acc[1]);
                        ulonglong2 w5 = w[5];
                        acc[2] = fma2(xv.y, w5.x, acc[2]);
                        acc[3] = fma2(xv.y, w5.y, acc[3]);
                        ulonglong2 w6 = w[6];
                        acc[4] = fma2(xv.y, w6.x, acc[4]);
                        acc[5] = fma2(xv.y, w6.y, acc[5]);
                        ulonglong2 w7 = w[7];
                        acc[6] = fma2(xv.y, w7.x, acc[6]);
                        acc[7] = fma2(xv.y, w7.y, acc[7]);
                    }
                }
            }
            __syncwarp();

            // refill the buffer just consumed
            if (c2 < 2) {
                produce(base, c2 + 2);                      // this group's other half
            } else {
                if (gn < ngroups) produce(basen, c2 - 2);   // next group's halves
            }
        }

        // ---- epilogue: this thread owns token base+lane (OOB zero-filled by TMA) ----
        const int tok = base + lane;
        if (tok < ntok) epilogue(acc, ep, out, tok);
    }
}

extern "C" void kernel_launch(void* const* d_in, const int* in_sizes, int n_in,
                              void* d_out, int out_size)
{
    const float* x     = (const float*)d_in[0];
    const float* W1    = (const float*)d_in[1];
    const float* b1    = (const float*)d_in[2];
    const float* W2    = (const float*)d_in[3];
    const float* b2    = (const float*)d_in[4];
    const float* gamma = (const float*)d_in[5];
    const float* beta  = (const float*)d_in[6];
    float* out = (float*)d_out;

    int ntok = in_sizes[0] / DIM;               // 262144 for the bench shape

    // ---- TMA descriptor: 3D view x[token][chunk][32 floats] ----
    typedef CUresult (*PFN_enc)(CUtensorMap*, CUtensorMapDataType, cuuint32_t, void*,
                                const cuuint64_t*, const cuuint64_t*, const cuuint32_t*,
                                const cuuint32_t*, CUtensorMapInterleave, CUtensorMapSwizzle,
                                CUtensorMapL2promotion, CUtensorMapFloatOOBfill);
    void* sym = nullptr;
    cudaDriverEntryPointQueryResult qst;
    cudaGetDriverEntryPoint("cuTensorMapEncodeTiled", &sym, cudaEnableDefault, &qst);
    PFN_enc enc = (PFN_enc)sym;

    CUtensorMap tmap;
    cuuint64_t dims[3]    = {32, 8, (cuuint64_t)ntok};       // floats, chunks, tokens
    cuuint64_t strides[2] = {128, (cuuint64_t)DIM * 4};      // chunk 128B, token 1024B
    cuuint32_t box[3]     = {32, 2, (cuuint32_t)TPW};        // 128B x 2 chunks x 32 tokens = 8KB
    cuuint32_t es[3]      = {1, 1, 1};
    enc(&tmap, CU_TENSOR_MAP_DATA_TYPE_FLOAT32, 3, (void*)x,
        dims, strides, box, es,
        CU_TENSOR_MAP_INTERLEAVE_NONE, CU_TENSOR_MAP_SWIZZLE_128B,
        CU_TENSOR_MAP_L2_PROMOTION_L2_128B, CU_TENSOR_MAP_FLOAT_OOB_FILL_NONE);

    int ngroups = (ntok + TPW - 1) / TPW;
    int blocks = 148;                            // persistent: 1 block/SM
    int maxb = (ngroups + WARPS - 1) / WARPS;
    if (blocks > maxb) blocks = maxb;
    if (blocks < 1) blocks = 1;

    cudaFuncSetAttribute(ffn_kernel, cudaFuncAttributeMaxDynamicSharedMemorySize, SMEM_TOTAL);
    ffn_kernel<<<blocks, 256, SMEM_TOTAL>>>(tmap, W1, b1, W2, b2, gamma, beta, out, ntok);
}

// round 15
// speedup vs baseline: 2.5789x; 1.5570x over previous
#include <cuda_runtime.h>
#include <cstdint>

#define DIM 256
#define OUT 8
#define CHUNK 32          // dims per pipeline chunk
#define NCHUNK 8          // DIM / CHUNK
#define ROWF 32           // floats per row (XOR piece swizzle handles banks)
#define TPW 32            // tokens per warp group (1 per lane)
#define WARPS 8           // warps per block
#define STAGES 3

#define STAGE_FLOATS (TPW * ROWF)                     // 1024
#define XBUF_FLOATS  (WARPS * STAGES * STAGE_FLOATS)  // 24576
#define XBUF_BYTES   (XBUF_FLOATS * 4)                // 98304
#define WP_BYTES     (DIM / 2 * OUT * 8)              // 8192
#define SMEM_TOTAL   (XBUF_BYTES + WP_BYTES + 96 * 4) // ~106.9KB -> 2 blocks/SM

__device__ __forceinline__ unsigned long long pk2(float lo, float hi) {
    unsigned long long r;
    asm("mov.b64 %0, {%1,%2};" : "=l"(r) : "f"(lo), "f"(hi));
    return r;
}
__device__ __forceinline__ unsigned long long fma2(unsigned long long a, unsigned long long b,
                                                   unsigned long long c) {
    unsigned long long d;
    asm("fma.rn.f32x2 %0, %1, %2, %3;" : "=l"(d) : "l"(a), "l"(b), "l"(c));
    return d;
}
__device__ __forceinline__ void cp16_ef(uint32_t saddr, const float* gptr, unsigned long long pol) {
    asm volatile("cp.async.cg.shared.global.L2::cache_hint [%0], [%1], 16, %2;"
                 :: "r"(saddr), "l"(gptr), "l"(pol));
}

struct EpiParams { const float *W2, *b1, *b2, *g, *bt; };

__device__ __forceinline__ void epilogue(const unsigned long long* acc, const EpiParams& ep,
                                         float* __restrict__ out, int tok)
{
    float gg[OUT];
    #pragma unroll
    for (int o = 0; o < OUT; o++) {
        float2 p = *(const float2*)&acc[o];
        float hv = p.x + p.y + ep.b1[o];
        gg[o] = 0.5f * hv * (1.0f + erff(hv * 0.70710678118654752440f));
    }
    float y[OUT];
    #pragma unroll
    for (int p = 0; p < OUT; p++) {
        float s = ep.b2[p];
        #pragma unroll
        for (int o = 0; o < OUT; o++) s = fmaf(ep.W2[p * 8 + o], gg[o], s);
        y[p] = s;
    }
    float mu = 0.0f;
    #pragma unroll
    for (int p = 0; p < OUT; p++) mu += y[p];
    mu *= 0.125f;
    float var = 0.0f;
    #pragma unroll
    for (int p = 0; p < OUT; p++) { float d = y[p] - mu; var = fmaf(d, d, var); }
    var *= 0.125f;
    float rs = rsqrtf(var + 1e-5f);

    float4 o0, o1;
    o0.x = (y[0] - mu) * rs * ep.g[0] + ep.bt[0];
    o0.y = (y[1] - mu) * rs * ep.g[1] + ep.bt[1];
    o0.z = (y[2] - mu) * rs * ep.g[2] + ep.bt[2];
    o0.w = (y[3] - mu) * rs * ep.g[3] + ep.bt[3];
    o1.x = (y[4] - mu) * rs * ep.g[4] + ep.bt[4];
    o1.y = (y[5] - mu) * rs * ep.g[5] + ep.bt[5];
    o1.z = (y[6] - mu) * rs * ep.g[6] + ep.bt[6];
    o1.w = (y[7] - mu) * rs * ep.g[7] + ep.bt[7];
    float* op = out + (size_t)tok * 8;
    // streaming stores: out is write-once, keep it out of L2's working set
    asm volatile("st.global.cs.v4.f32 [%0], {%1,%2,%3,%4};"
                 :: "l"(op), "f"(o0.x), "f"(o0.y), "f"(o0.z), "f"(o0.w));
    asm volatile("st.global.cs.v4.f32 [%0], {%1,%2,%3,%4};"
                 :: "l"(op + 4), "f"(o1.x), "f"(o1.y), "f"(o1.z), "f"(o1.w));
}

__global__ __launch_bounds__(256, 2)
void ffn_kernel(const float* __restrict__ x, const float* __restrict__ W1,
                const float* __restrict__ b1, const float* __restrict__ W2,
                const float* __restrict__ b2, const float* __restrict__ gamma,
                const float* __restrict__ beta, float* __restrict__ out, int ntok)
{
    extern __shared__ char smem_raw[];
    float* xbuf = (float*)smem_raw;
    unsigned long long* Wp = (unsigned long long*)(smem_raw + XBUF_BYTES);
    float* tail = (float*)(smem_raw + XBUF_BYTES + WP_BYTES);
    float* sW2 = tail;          // 64
    float* sb1 = tail + 64;     // 8
    float* sb2 = tail + 72;     // 8
    float* sg  = tail + 80;     // 8
    float* sbt = tail + 88;     // 8

    const int tid = threadIdx.x;

    // ---- one-time init: packed W1 dim-pairs Wp[dp*8+o] = {W1[o][2dp], W1[o][2dp+1]} ----
    {
        int e = tid * 4;
        #pragma unroll
        for (int q = 0; q < 4; q++) {
            int idx = e + q;
            int d = idx >> 3;
            int o = idx & 7;
            Wp[idx] = pk2(W1[o * DIM + 2 * d], W1[o * DIM + 2 * d + 1]);
        }
        if (tid < 64) sW2[tid] = W2[tid];
        if (tid < 8) { sb1[tid] = b1[tid]; sb2[tid] = b2[tid]; sg[tid] = gamma[tid]; sbt[tid] = beta[tid]; }
    }
    __syncthreads();

    const int lane = tid & 31;
    const int warp = tid >> 5;
    const int warp_global = blockIdx.x * WARPS + warp;
    const int nwarps = gridDim.x * WARPS;
    const int ngroups = (ntok + TPW - 1) / TPW;

    float* wtile = xbuf + warp * STAGES * STAGE_FLOATS;
    const uint32_t wtile_su = (uint32_t)__cvta_generic_to_shared(wtile);
    EpiParams ep{sW2, sb1, sb2, sg, sbt};

    // L2 evict_first policy for the use-once x stream
    unsigned long long pol;
    asm("createpolicy.fractional.L2::evict_first.b64 %0, 1.0;" : "=l"(pol));

    // staging split: lin = it*32+lane, r = lin>>3 (token row), j = lin&7 (16B piece)
    // physical piece = j ^ (r&7): conflict-free on write and on read (R7-proven)
    const int r0 = lane >> 3, j0 = lane & 7;
    const ulonglong2* Wp2 = (const ulonglong2*)Wp;

    for (int g = warp_global; g < ngroups; g += nwarps) {
        const int base = g * TPW;
        const bool full = (base + TPW) <= ntok;
        const float* xg = x + (size_t)base * DIM;

        // ---- issue chunk c into stage stg ----
        auto stage_cp = [&](int c, int stg) {
            const uint32_t sbase = wtile_su + (uint32_t)(stg * STAGE_FLOATS) * 4;
            if (full) {
                #pragma unroll
                for (int it = 0; it < 8; it++) {
                    int r = it * 4 + r0;
                    int pj = j0 ^ (r & 7);
                    cp16_ef(sbase + (uint32_t)(r * ROWF + pj * 4) * 4,
                            xg + (size_t)r * DIM + c * CHUNK + j0 * 4, pol);
                }
            } else {
                #pragma unroll
                for (int it = 0; it < 8; it++) {
                    int r = it * 4 + r0;
                    int pj = j0 ^ (r & 7);
                    if (base + r < ntok)
                        cp16_ef(sbase + (uint32_t)(r * ROWF + pj * 4) * 4,
                                xg + (size_t)r * DIM + c * CHUNK + j0 * 4, pol);
                }
            }
            asm volatile("cp.async.commit_group;");
        };

        unsigned long long acc[OUT];
        #pragma unroll
        for (int o = 0; o < OUT; o++) acc[o] = 0ull;

        const float* myrow = wtile + lane * ROWF;
        const int l7 = lane & 7;

        // ---- compute chunk c from stage stg ----
        auto compute = [&](int c, int stg) {
            const float* r = myrow + stg * STAGE_FLOATS;
            #pragma unroll
            for (int i = 0; i < 8; i++) {
                ulonglong2 xv = *(const ulonglong2*)(r + ((i ^ l7) << 2));
                const int dpg = c * 16 + 2 * i;
                const ulonglong2* w = Wp2 + (size_t)dpg * 4;
                {
                    ulonglong2 w0 = w[0];
                    acc[0] = fma2(xv.x, w0.x, acc[0]);
                    acc[1] = fma2(xv.x, w0.y, acc[1]);
                    ulonglong2 w1 = w[1];
                    acc[2] = fma2(xv.x, w1.x, acc[2]);
                    acc[3] = fma2(xv.x, w1.y, acc[3]);
                    ulonglong2 w2 = w[2];
                    acc[4] = fma2(xv.x, w2.x, acc[4]);
                    acc[5] = fma2(xv.x, w2.y, acc[5]);
                    ulonglong2 w3 = w[3];
                    acc[6] = fma2(xv.x, w3.x, acc[6]);
                    acc[7] = fma2(xv.x, w3.y, acc[7]);
                }
                {
                    ulonglong2 w4 = w[4];
                    acc[0] = fma2(xv.y, w4.x, acc[0]);
                    acc[1] = fma2(xv.y, w4.y, acc[1]);
                    ulonglong2 w5 = w[5];
                    acc[2] = fma2(xv.y, w5.x, acc[2]);
                    acc[3] = fma2(xv.y, w5.y, acc[3]);
                    ulonglong2 w6 = w[6];
                    acc[4] = fma2(xv.y, w6.x, acc[4]);
                    acc[5] = fma2(xv.y, w6.y, acc[5]);
                    ulonglong2 w7 = w[7];
                    acc[6] = fma2(xv.y, w7.x, acc[6]);
                    acc[7] = fma2(xv.y, w7.y, acc[7]);
                }
            }
        };

        // ---- 3-stage pipeline, prefetch distance 2 ----
        stage_cp(0, 0);
        stage_cp(1, 1);
        #pragma unroll
        for (int c = 0; c < NCHUNK; c++) {
            if (c + 2 < NCHUNK) {
                stage_cp(c + 2, (c + 2) % STAGES);
                asm volatile("cp.async.wait_group 2;");
            } else if (c + 1 < NCHUNK) {
                asm volatile("cp.async.wait_group 1;");
            } else {
                asm volatile("cp.async.wait_group 0;");
            }
            __syncwarp();
            compute(c, c % STAGES);
            __syncwarp();
        }

        // ---- epilogue: this thread owns token base+lane ----
        const int tok = base + lane;
        if (tok < ntok) epilogue(acc, ep, out, tok);
        __syncwarp();   // protect tile reuse across group iterations
    }
}

extern "C" void kernel_launch(void* const* d_in, const int* in_sizes, int n_in,
                              void* d_out, int out_size)
{
    const float* x     = (const float*)d_in[0];
    const float* W1    = (const float*)d_in[1];
    const float* b1    = (const float*)d_in[2];
    const float* W2    = (const float*)d_in[3];
    const float* b2    = (const float*)d_in[4];
    const float* gamma = (const float*)d_in[5];
    const float* beta  = (const float*)d_in[6];
    float* out = (float*)d_out;

    int ntok = in_sizes[0] / DIM;               // 262144 for the bench shape
    int ngroups = (ntok + TPW - 1) / TPW;       // warp-groups of 32 tokens
    int blocks = (ngroups + WARPS - 1) / WARPS;
    if (blocks > 1024) blocks = 1024;
    if (blocks < 1) blocks = 1;

    cudaFuncSetAttribute(ffn_kernel, cudaFuncAttributeMaxDynamicSharedMemorySize, SMEM_TOTAL);
    ffn_kernel<<<blocks, 256, SMEM_TOTAL>>>(x, W1, b1, W2, b2, gamma, beta, out, ntok);
}

// round 16
// speedup vs baseline: 2.7001x; 1.0470x over previous
#include <cuda_runtime.h>
#include <cstdint>

#define DIM 256
#define OUT 8
#define CHUNK 32          // dims per pipeline chunk
#define NCHUNK 8          // DIM / CHUNK
#define ROWF 32           // floats per row (XOR piece swizzle handles banks)
#define TPG 64            // tokens per warp group (2 per lane)
#define WARPS 4           // warps per block (128 threads)
#define STAGES 3

#define STAGE_FLOATS (TPG * ROWF)                     // 2048 (8KB)
#define XBUF_FLOATS  (WARPS * STAGES * STAGE_FLOATS)  // 24576
#define XBUF_BYTES   (XBUF_FLOATS * 4)                // 98304
#define WP_BYTES     (DIM / 2 * OUT * 8)              // 8192
#define SMEM_TOTAL   (XBUF_BYTES + WP_BYTES + 96 * 4) // ~106.9KB -> 2 blocks/SM

__device__ __forceinline__ unsigned long long pk2(float lo, float hi) {
    unsigned long long r;
    asm("mov.b64 %0, {%1,%2};" : "=l"(r) : "f"(lo), "f"(hi));
    return r;
}
__device__ __forceinline__ unsigned long long fma2(unsigned long long a, unsigned long long b,
                                                   unsigned long long c) {
    unsigned long long d;
    asm("fma.rn.f32x2 %0, %1, %2, %3;" : "=l"(d) : "l"(a), "l"(b), "l"(c));
    return d;
}
__device__ __forceinline__ void cp16_ef(uint32_t saddr, const float* gptr, unsigned long long pol) {
    asm volatile("cp.async.cg.shared.global.L2::cache_hint [%0], [%1], 16, %2;"
                 :: "r"(saddr), "l"(gptr), "l"(pol));
}

struct EpiParams { const float *W2, *b1, *b2, *g, *bt; };

__device__ __forceinline__ void epilogue(const unsigned long long* acc, const EpiParams& ep,
                                         float* __restrict__ out, int tok)
{
    float gg[OUT];
    #pragma unroll
    for (int o = 0; o < OUT; o++) {
        float2 p = *(const float2*)&acc[o];
        float hv = p.x + p.y + ep.b1[o];
        gg[o] = 0.5f * hv * (1.0f + erff(hv * 0.70710678118654752440f));
    }
    float y[OUT];
    #pragma unroll
    for (int p = 0; p < OUT; p++) {
        float s = ep.b2[p];
        #pragma unroll
        for (int o = 0; o < OUT; o++) s = fmaf(ep.W2[p * 8 + o], gg[o], s);
        y[p] = s;
    }
    float mu = 0.0f;
    #pragma unroll
    for (int p = 0; p < OUT; p++) mu += y[p];
    mu *= 0.125f;
    float var = 0.0f;
    #pragma unroll
    for (int p = 0; p < OUT; p++) { float d = y[p] - mu; var = fmaf(d, d, var); }
    var *= 0.125f;
    float rs = rsqrtf(var + 1e-5f);

    float4 o0, o1;
    o0.x = (y[0] - mu) * rs * ep.g[0] + ep.bt[0];
    o0.y = (y[1] - mu) * rs * ep.g[1] + ep.bt[1];
    o0.z = (y[2] - mu) * rs * ep.g[2] + ep.bt[2];
    o0.w = (y[3] - mu) * rs * ep.g[3] + ep.bt[3];
    o1.x = (y[4] - mu) * rs * ep.g[4] + ep.bt[4];
    o1.y = (y[5] - mu) * rs * ep.g[5] + ep.bt[5];
    o1.z = (y[6] - mu) * rs * ep.g[6] + ep.bt[6];
    o1.w = (y[7] - mu) * rs * ep.g[7] + ep.bt[7];
    float* op = out + (size_t)tok * 8;
    asm volatile("st.global.cs.v4.f32 [%0], {%1,%2,%3,%4};"
                 :: "l"(op), "f"(o0.x), "f"(o0.y), "f"(o0.z), "f"(o0.w));
    asm volatile("st.global.cs.v4.f32 [%0], {%1,%2,%3,%4};"
                 :: "l"(op + 4), "f"(o1.x), "f"(o1.y), "f"(o1.z), "f"(o1.w));
}

__global__ __launch_bounds__(128, 2)
void ffn_kernel(const float* __restrict__ x, const float* __restrict__ W1,
                const float* __restrict__ b1, const float* __restrict__ W2,
                const float* __restrict__ b2, const float* __restrict__ gamma,
                const float* __restrict__ beta, float* __restrict__ out, int ntok)
{
    extern __shared__ char smem_raw[];
    float* xbuf = (float*)smem_raw;
    unsigned long long* Wp = (unsigned long long*)(smem_raw + XBUF_BYTES);
    float* tail = (float*)(smem_raw + XBUF_BYTES + WP_BYTES);
    float* sW2 = tail;          // 64
    float* sb1 = tail + 64;     // 8
    float* sb2 = tail + 72;     // 8
    float* sg  = tail + 80;     // 8
    float* sbt = tail + 88;     // 8

    const int tid = threadIdx.x;

    // ---- one-time init: packed W1 dim-pairs Wp[dp*8+o] = {W1[o][2dp], W1[o][2dp+1]} ----
    {
        int e = tid * 8;                // 128 threads x 8 = 1024 entries
        #pragma unroll
        for (int q = 0; q < 8; q++) {
            int idx = e + q;
            int d = idx >> 3;
            int o = idx & 7;
            Wp[idx] = pk2(W1[o * DIM + 2 * d], W1[o * DIM + 2 * d + 1]);
        }
        if (tid < 64) sW2[tid] = W2[tid];
        if (tid < 8) { sb1[tid] = b1[tid]; sb2[tid] = b2[tid]; sg[tid] = gamma[tid]; sbt[tid] = beta[tid]; }
    }
    __syncthreads();

    const int lane = tid & 31;
    const int warp = tid >> 5;
    const int warp_global = blockIdx.x * WARPS + warp;
    const int nwarps = gridDim.x * WARPS;
    const int ngroups = (ntok + TPG - 1) / TPG;

    float* wtile = xbuf + warp * STAGES * STAGE_FLOATS;
    const uint32_t wtile_su = (uint32_t)__cvta_generic_to_shared(wtile);
    EpiParams ep{sW2, sb1, sb2, sg, sbt};

    // L2 evict_first policy for the use-once x stream
    unsigned long long pol;
    asm("createpolicy.fractional.L2::evict_first.b64 %0, 1.0;" : "=l"(pol));

    // staging: 64 rows x 8 pieces of 16B per stage; lane covers rows it*4+(lane>>3),
    // piece j0 = lane&7 at physical piece j0^(r&7) (conflict-free write + read)
    const int r0 = lane >> 3, j0 = lane & 7;
    const ulonglong2* Wp2 = (const ulonglong2*)Wp;

    for (int g = warp_global; g < ngroups; g += nwarps) {
        const int base = g * TPG;
        const bool full = (base + TPG) <= ntok;
        const float* xg = x + (size_t)base * DIM;

        // ---- issue chunk c into stage stg (64 rows x 128B = 8KB) ----
        auto stage_cp = [&](int c, int stg) {
            const uint32_t sbase = wtile_su + (uint32_t)(stg * STAGE_FLOATS) * 4;
            if (full) {
                #pragma unroll
                for (int it = 0; it < 16; it++) {
                    int r = it * 4 + r0;
                    int pj = j0 ^ (r & 7);
                    cp16_ef(sbase + (uint32_t)(r * ROWF + pj * 4) * 4,
                            xg + (size_t)r * DIM + c * CHUNK + j0 * 4, pol);
                }
            } else {
                #pragma unroll
                for (int it = 0; it < 16; it++) {
                    int r = it * 4 + r0;
                    int pj = j0 ^ (r & 7);
                    if (base + r < ntok)
                        cp16_ef(sbase + (uint32_t)(r * ROWF + pj * 4) * 4,
                                xg + (size_t)r * DIM + c * CHUNK + j0 * 4, pol);
                }
            }
            asm volatile("cp.async.commit_group;");
        };

        unsigned long long accA[OUT], accB[OUT];
        #pragma unroll
        for (int o = 0; o < OUT; o++) { accA[o] = 0ull; accB[o] = 0ull; }

        const float* rowA = xbuf + warp * STAGES * STAGE_FLOATS + lane * ROWF;
        const float* rowB = rowA + 32 * ROWF;
        const int lA = lane & 7;
        const int lB = (lane + 32) & 7;     // == lA, but keep separate for clarity

        // ---- compute chunk c from stage stg: 2 tokens per thread ----
        auto compute = [&](int c, int stg) {
            const float* rA = rowA + stg * STAGE_FLOATS;
            const float* rB = rowB + stg * STAGE_FLOATS;
            #pragma unroll
            for (int i = 0; i < 8; i++) {
                ulonglong2 xa = *(const ulonglong2*)(rA + ((i ^ lA) << 2));
                ulonglong2 xb = *(const ulonglong2*)(rB + ((i ^ lB) << 2));
                const int dpg = c * 16 + 2 * i;
                const ulonglong2* w = Wp2 + (size_t)dpg * 4;
                {
                    ulonglong2 w0 = w[0];
                    accA[0] = fma2(xa.x, w0.x, accA[0]);  accB[0] = fma2(xb.x, w0.x, accB[0]);
                    accA[1] = fma2(xa.x, w0.y, accA[1]);  accB[1] = fma2(xb.x, w0.y, accB[1]);
                    ulonglong2 w1 = w[1];
                    accA[2] = fma2(xa.x, w1.x, accA[2]);  accB[2] = fma2(xb.x, w1.x, accB[2]);
                    accA[3] = fma2(xa.x, w1.y, accA[3]);  accB[3] = fma2(xb.x, w1.y, accB[3]);
                    ulonglong2 w2 = w[2];
                    accA[4] = fma2(xa.x, w2.x, accA[4]);  accB[4] = fma2(xb.x, w2.x, accB[4]);
                    accA[5] = fma2(xa.x, w2.y, accA[5]);  accB[5] = fma2(xb.x, w2.y, accB[5]);
                    ulonglong2 w3 = w[3];
                    accA[6] = fma2(xa.x, w3.x, accA[6]);  accB[6] = fma2(xb.x, w3.x, accB[6]);
                    accA[7] = fma2(xa.x, w3.y, accA[7]);  accB[7] = fma2(xb.x, w3.y, accB[7]);
                }
                {
                    ulonglong2 w4 = w[4];
                    accA[0] = fma2(xa.y, w4.x, accA[0]);  accB[0] = fma2(xb.y, w4.x, accB[0]);
                    accA[1] = fma2(xa.y, w4.y, accA[1]);  accB[1] = fma2(xb.y, w4.y, accB[1]);
                    ulonglong2 w5 = w[5];
                    accA[2] = fma2(xa.y, w5.x, accA[2]);  accB[2] = fma2(xb.y, w5.x, accB[2]);
                    accA[3] = fma2(xa.y, w5.y, accA[3]);  accB[3] = fma2(xb.y, w5.y, accB[3]);
                    ulonglong2 w6 = w[6];
                    accA[4] = fma2(xa.y, w6.x, accA[4]);  accB[4] = fma2(xb.y, w6.x, accB[4]);
                    accA[5] = fma2(xa.y, w6.y, accA[5]);  accB[5] = fma2(xb.y, w6.y, accB[5]);
                    ulonglong2 w7 = w[7];
                    accA[6] = fma2(xa.y, w7.x, accA[6]);  accB[6] = fma2(xb.y, w7.x, accB[6]);
                    accA[7] = fma2(xa.y, w7.y, accA[7]);  accB[7] = fma2(xb.y, w7.y, accB[7]);
                }
            }
        };

        // ---- 3-stage pipeline, prefetch distance 2 ----
        stage_cp(0, 0);
        stage_cp(1, 1);
        #pragma unroll
        for (int c = 0; c < NCHUNK; c++) {
            if (c + 2 < NCHUNK) {
                stage_cp(c + 2, (c + 2) % STAGES);
                asm volatile("cp.async.wait_group 2;");
            } else if (c + 1 < NCHUNK) {
                asm volatile("cp.async.wait_group 1;");
            } else {
                asm volatile("cp.async.wait_group 0;");
            }
            __syncwarp();
            compute(c, c % STAGES);
            __syncwarp();
        }

        // ---- epilogue: this thread owns tokens base+lane, base+32+lane ----
        const int tokA = base + lane;
        const int tokB = base + 32 + lane;
        if (tokA < ntok) epilogue(accA, ep, out, tokA);
        if (tokB < ntok) epilogue(accB, ep, out, tokB);
        __syncwarp();   // protect tile reuse across group iterations
    }
}

extern "C" void kernel_launch(void* const* d_in, const int* in_sizes, int n_in,
                              void* d_out, int out_size)
{
    const float* x     = (const float*)d_in[0];
    const float* W1    = (const float*)d_in[1];
    const float* b1    = (const float*)d_in[2];
    const float* W2    = (const float*)d_in[3];
    const float* b2    = (const float*)d_in[4];
    const float* gamma = (const float*)d_in[5];
    const float* beta  = (const float*)d_in[6];
    float* out = (float*)d_out;

    int ntok = in_sizes[0] / DIM;               // 262144 for the bench shape
    int ngroups = (ntok + TPG - 1) / TPG;       // warp-groups of 64 tokens
    int blocks = (ngroups + WARPS - 1) / WARPS;
    if (blocks > 2048) blocks = 2048;
    if (blocks < 1) blocks = 1;

    cudaFuncSetAttribute(ffn_kernel, cudaFuncAttributeMaxDynamicSharedMemorySize, SMEM_TOTAL);
    ffn_kernel<<<blocks, 128, SMEM_TOTAL>>>(x, W1, b1, W2, b2, gamma, beta, out, ntok);
}